// round 6
// baseline (speedup 1.0000x reference)
#include <cuda_runtime.h>
#include <cuda_bf16.h>
#include <math.h>
#include <stdint.h>

// ---------------- problem constants ----------------------------------------
#define BSZ 2
#define TT 2048
#define DM 1024
#define DI 2048
#define NH 8
#define DS 64
#define DH 256
#define NROWS (BSZ*TT)          // 4096
#define EPSV 1e-6f
#define NCATP 1280              // B(512) | C(512) | dt(8) | pad

// ---------------- scratch (device globals) ---------------------------------
__device__ __nv_bfloat16 g_xn[(size_t)NROWS * DM];
__device__ float         g_xz[(size_t)NROWS * 2 * DI];
__device__ __nv_bfloat16 g_xs[(size_t)NROWS * DI];
__device__ float         g_bcdt[(size_t)NROWS * NCATP];
__device__ float         g_dt[(size_t)NROWS * NH];
__device__ __nv_bfloat16 g_y [(size_t)NROWS * DI];
__device__ __nv_bfloat16 g_inw [(size_t)(2*DI) * DM];
__device__ __nv_bfloat16 g_wcat[(size_t)NCATP * DI];
__device__ __nv_bfloat16 g_outw[(size_t)DM * DI];

// ---------------- PTX helpers ----------------------------------------------
__device__ __forceinline__ uint32_t smem_u32(const void* p) {
    uint32_t a;
    asm("{ .reg .u64 t; cvta.to.shared.u64 t, %1; cvt.u32.u64 %0, t; }" : "=r"(a) : "l"(p));
    return a;
}

#define CP_ASYNC16(dst, src) \
    asm volatile("cp.async.cg.shared.global [%0], [%1], 16;" :: "r"(dst), "l"(src) : "memory")
#define CP_COMMIT() asm volatile("cp.async.commit_group;" ::: "memory")

#define LDM_X4(r0, r1, r2, r3, addr) \
    asm volatile("ldmatrix.sync.aligned.m8n8.x4.shared.b16 {%0,%1,%2,%3}, [%4];" \
                 : "=r"(r0), "=r"(r1), "=r"(r2), "=r"(r3) : "r"(addr))

#define MMA16816(d, a0, a1, a2, a3, b0, b1) \
    asm volatile("mma.sync.aligned.m16n8k16.row.col.f32.bf16.bf16.f32 " \
                 "{%0,%1,%2,%3}, {%4,%5,%6,%7}, {%8,%9}, {%0,%1,%2,%3};" \
                 : "+f"((d)[0]), "+f"((d)[1]), "+f"((d)[2]), "+f"((d)[3]) \
                 : "r"(a0), "r"(a1), "r"(a2), "r"(a3), "r"(b0), "r"(b1))

// ---------------- bf16 mma.sync GEMM: C[M,N] = A[M,K] @ W[N,K]^T (+Res) ----
// BM=128, BN=256, BK=32, 256 threads, 8 warps (2x4), warp tile 64x64,
// 4-stage cp.async pipeline.
#define BM 128
#define BN2 256
#define BKK 32
#define ROWE 40        // smem row stride in bf16 elements (32 + 8 pad)
#define ROWB 80        // bytes
#define SA_BYTES (BM  * ROWB)               // 10240
#define SB_BYTES (BN2 * ROWB)               // 20480
#define STG_BYTES (SA_BYTES + SB_BYTES)     // 30720
#define NSTAGE 4
#define GEMM_SMEM (NSTAGE * STG_BYTES)      // 122880

template <bool ADD_RES>
__global__ void __launch_bounds__(256)
gemm_mma(const __nv_bfloat16* __restrict__ A, const __nv_bfloat16* __restrict__ W,
         float* __restrict__ C, const float* __restrict__ Res,
         int M, int N, int K)
{
    extern __shared__ char sm[];
    uint32_t base = smem_u32(sm);

    int tid = threadIdx.x;
    int wid = tid >> 5, lane = tid & 31;
    int wm = wid >> 2, wn = wid & 3;          // 2 x 4 warp grid, tile 64x64
    int m0 = blockIdx.y * BM;
    int n0 = blockIdx.x * BN2;

    const __nv_bfloat16* Ag = A + (size_t)m0 * K;
    const __nv_bfloat16* Wg = W + (size_t)n0 * K;

    float acc[4][8][4];
    #pragma unroll
    for (int i = 0; i < 4; i++)
        #pragma unroll
        for (int j = 0; j < 8; j++)
            #pragma unroll
            for (int f = 0; f < 4; f++) acc[i][j][f] = 0.f;

    int nk = K / BKK;

    // stage loader: A = 512 16B chunks, B = 1024 16B chunks
    auto load_stage = [&](int s, int k0) {
        uint32_t sA = base + s * STG_BYTES;
        uint32_t sB = sA + SA_BYTES;
        #pragma unroll
        for (int i = tid; i < 512; i += 256) {
            int r = i >> 2, c = i & 3;
            CP_ASYNC16(sA + r * ROWB + c * 16, Ag + (size_t)r * K + k0 + c * 8);
        }
        #pragma unroll
        for (int i = tid; i < 1024; i += 256) {
            int r = i >> 2, c = i & 3;
            CP_ASYNC16(sB + r * ROWB + c * 16, Wg + (size_t)r * K + k0 + c * 8);
        }
    };

    // prologue: stages 0..2  (stage s lives in commit-group s)
    for (int s = 0; s < 3; s++) { load_stage(s, s * BKK); CP_COMMIT(); }

    for (int kt = 0; kt < nk; kt++) {
        if (kt + 3 < nk) load_stage((kt + 3) & 3, (kt + 3) * BKK);
        CP_COMMIT();                                  // commit-group 3+kt (maybe empty)
        asm volatile("cp.async.wait_group 3;" ::: "memory");   // stage kt complete
        __syncthreads();

        uint32_t sA = base + (kt & 3) * STG_BYTES;
        uint32_t sB = sA + SA_BYTES;

        #pragma unroll
        for (int ks = 0; ks < 2; ks++) {
            int colb = (ks * 16 + (lane >> 4) * 8) * 2;
            uint32_t a[4][4], b[4][4];
            #pragma unroll
            for (int i = 0; i < 4; i++) {
                int row = wm * 64 + i * 16 + (lane & 15);
                LDM_X4(a[i][0], a[i][1], a[i][2], a[i][3],
                       sA + (uint32_t)(row * ROWB + colb));
            }
            #pragma unroll
            for (int jj = 0; jj < 4; jj++) {
                int row = wn * 64 + jj * 16 + (lane & 15);
                LDM_X4(b[jj][0], b[jj][1], b[jj][2], b[jj][3],
                       sB + (uint32_t)(row * ROWB + colb));
            }
            #pragma unroll
            for (int i = 0; i < 4; i++)
                #pragma unroll
                for (int jj = 0; jj < 4; jj++) {
                    MMA16816(acc[i][jj * 2],     a[i][0], a[i][1], a[i][2], a[i][3],
                             b[jj][0], b[jj][2]);
                    MMA16816(acc[i][jj * 2 + 1], a[i][0], a[i][1], a[i][2], a[i][3],
                             b[jj][1], b[jj][3]);
                }
        }
        __syncthreads();
    }

    // epilogue: direct register -> gmem (float2 per c-frag half)
    int gid = lane >> 2, t4 = lane & 3;
    #pragma unroll
    for (int i = 0; i < 4; i++) {
        int row0 = m0 + wm * 64 + i * 16 + gid;
        #pragma unroll
        for (int j = 0; j < 8; j++) {
            int col = n0 + wn * 64 + j * 8 + t4 * 2;
            size_t i0 = (size_t)row0 * N + col;
            size_t i1 = (size_t)(row0 + 8) * N + col;
            float2 v0 = make_float2(acc[i][j][0], acc[i][j][1]);
            float2 v1 = make_float2(acc[i][j][2], acc[i][j][3]);
            if (ADD_RES) {
                float2 r0 = *(const float2*)(Res + i0);
                float2 r1 = *(const float2*)(Res + i1);
                v0.x += r0.x; v0.y += r0.y;
                v1.x += r1.x; v1.y += r1.y;
            }
            *(float2*)(C + i0) = v0;
            *(float2*)(C + i1) = v1;
        }
    }
}

// ---------------- weight conversion ----------------------------------------
__global__ void cvt_bf16_k(const float* __restrict__ in, __nv_bfloat16* __restrict__ out, int n)
{
    for (int i = blockIdx.x * 256 + threadIdx.x; i < n; i += gridDim.x * 256)
        out[i] = __float2bfloat16(in[i]);
}

__global__ void build_wcat_k(const float* __restrict__ Bw, const float* __restrict__ Cw,
                             const float* __restrict__ dtw)
{
    int n = NCATP * DI;
    for (int i = blockIdx.x * 256 + threadIdx.x; i < n; i += gridDim.x * 256) {
        int r = i >> 11, k = i & (DI - 1);
        float v;
        if (r < 512)       v = Bw[(size_t)r * DI + k];
        else if (r < 1024) v = Cw[(size_t)(r - 512) * DI + k];
        else if (r < 1032) v = dtw[(size_t)(r - 1024) * DI + k];
        else               v = 0.f;
        g_wcat[i] = __float2bfloat16(v);
    }
}

// ---------------- RMSNorm (writes bf16) -------------------------------------
__global__ void rmsnorm_k(const float* __restrict__ x, const float* __restrict__ w)
{
    int row = blockIdx.x;
    const float* xr = x + (size_t)row * DM;
    float s = 0.f;
    for (int i = threadIdx.x; i < DM; i += 256) { float v = xr[i]; s += v * v; }
    __shared__ float red[8];
    #pragma unroll
    for (int o = 16; o; o >>= 1) s += __shfl_xor_sync(0xffffffffu, s, o);
    if ((threadIdx.x & 31) == 0) red[threadIdx.x >> 5] = s;
    __syncthreads();
    if (threadIdx.x < 8) {
        float v = red[threadIdx.x];
        #pragma unroll
        for (int o = 4; o; o >>= 1) v += __shfl_xor_sync(0xffu, v, o);
        if (threadIdx.x == 0) red[0] = rsqrtf(v / (float)DM + EPSV);
    }
    __syncthreads();
    float sc = red[0];
    for (int i = threadIdx.x; i < DM; i += 256)
        g_xn[(size_t)row * DM + i] = __float2bfloat16(xr[i] * sc * w[i]);
}

// ---------------- causal depthwise conv (K=4) + bias + SiLU -> bf16 ---------
__global__ void conv_silu_k(const float* __restrict__ cw, const float* __restrict__ cb)
{
    int c = blockIdx.x * 256 + threadIdx.x;
    int t = blockIdx.y;
    int b = blockIdx.z;
    float4 w = ((const float4*)cw)[c];
    float acc = cb[c];
    size_t colbase = (size_t)b * TT * (2 * DI) + c;
    const size_t stride = 2 * DI;
    if (t >= 3) acc += w.x * g_xz[colbase + (size_t)(t - 3) * stride];
    if (t >= 2) acc += w.y * g_xz[colbase + (size_t)(t - 2) * stride];
    if (t >= 1) acc += w.z * g_xz[colbase + (size_t)(t - 1) * stride];
    acc += w.w * g_xz[colbase + (size_t)t * stride];
    float sig = 1.f / (1.f + expf(-acc));
    g_xs[((size_t)b * TT + t) * DI + c] = __float2bfloat16(acc * sig);
}

// ---------------- dt finalize: softplus(raw + bias) -------------------------
__global__ void dt_fin_k(const float* __restrict__ dtb)
{
    int i = blockIdx.x * 256 + threadIdx.x;
    if (i < NROWS * NH) {
        int row = i >> 3, h = i & 7;
        float v = g_bcdt[(size_t)row * NCATP + 1024 + h] + dtb[h];
        g_dt[i] = (v > 20.f) ? v : log1pf(expf(v));
    }
}

// ---------------- selective scan + D-skip + SiLU(z) gating -> bf16 ----------
__global__ void __launch_bounds__(256)
scan_k(const float* __restrict__ A_log, const float* __restrict__ Dp)
{
    int dtile = blockIdx.x;
    int h = blockIdx.y;
    int b = blockIdx.z;
    int warp = threadIdx.x >> 5, lane = threadIdx.x & 31;
    int dl = lane & 3;
    int ng = lane >> 2;
    int d = dtile * 32 + warp * 4 + dl;
    int nbase = ng * 8;

    float A = -expf(A_log[h]);
    float Dh = Dp[h];
    float hs[8];
    #pragma unroll
    for (int j = 0; j < 8; j++) hs[j] = 0.f;

    size_t rb = (size_t)b * TT;
    size_t bcoff = (size_t)h * DS + nbase;
    size_t ccoff = 512 + bcoff;
    int xoff = h * DH + d;

    size_t row = rb;
    float dtv = g_dt[row * NH + h];
    const float* Bp = g_bcdt + row * NCATP + bcoff;
    const float* Cp = g_bcdt + row * NCATP + ccoff;
    float4 b0 = *(const float4*)(Bp);
    float4 b1 = *(const float4*)(Bp + 4);
    float4 c0 = *(const float4*)(Cp);
    float4 c1 = *(const float4*)(Cp + 4);
    float xd = __bfloat162float(g_xs[row * DI + xoff]);
    float zv = (ng == 0) ? g_xz[row * (2 * DI) + DI + xoff] : 0.f;

    for (int t = 0; t < TT; t++) {
        float n_dt = 0.f, n_xd = 0.f, n_zv = 0.f;
        float4 nb0 = b0, nb1 = b1, nc0 = c0, nc1 = c1;
        if (t + 1 < TT) {
            size_t nrow = rb + t + 1;
            n_dt = g_dt[nrow * NH + h];
            const float* nBp = g_bcdt + nrow * NCATP + bcoff;
            const float* nCp = g_bcdt + nrow * NCATP + ccoff;
            nb0 = *(const float4*)(nBp);
            nb1 = *(const float4*)(nBp + 4);
            nc0 = *(const float4*)(nCp);
            nc1 = *(const float4*)(nCp + 4);
            n_xd = __bfloat162float(g_xs[nrow * DI + xoff]);
            if (ng == 0) n_zv = g_xz[nrow * (2 * DI) + DI + xoff];
        }

        float dA = __expf(dtv * A);
        float dtx = dtv * xd;
        float acc;
        hs[0] = dA * hs[0] + b0.x * dtx; acc  = c0.x * hs[0];
        hs[1] = dA * hs[1] + b0.y * dtx; acc += c0.y * hs[1];
        hs[2] = dA * hs[2] + b0.z * dtx; acc += c0.z * hs[2];
        hs[3] = dA * hs[3] + b0.w * dtx; acc += c0.w * hs[3];
        hs[4] = dA * hs[4] + b1.x * dtx; acc += c1.x * hs[4];
        hs[5] = dA * hs[5] + b1.y * dtx; acc += c1.y * hs[5];
        hs[6] = dA * hs[6] + b1.z * dtx; acc += c1.z * hs[6];
        hs[7] = dA * hs[7] + b1.w * dtx; acc += c1.w * hs[7];

        acc += __shfl_xor_sync(0xffffffffu, acc, 16);
        acc += __shfl_xor_sync(0xffffffffu, acc, 8);
        acc += __shfl_xor_sync(0xffffffffu, acc, 4);

        if (ng == 0) {
            float sig = 1.f / (1.f + __expf(-zv));
            g_y[(rb + t) * DI + xoff] = __float2bfloat16((acc + Dh * xd) * (zv * sig));
        }

        dtv = n_dt; xd = n_xd; zv = n_zv;
        b0 = nb0; b1 = nb1; c0 = nc0; c1 = nc1;
    }
}

// ---------------- launch ----------------------------------------------------
extern "C" void kernel_launch(void* const* d_in, const int* in_sizes, int n_in,
                              void* d_out, int out_size)
{
    const float* x      = (const float*)d_in[0];
    const float* norm_w = (const float*)d_in[1];
    const float* in_w   = (const float*)d_in[2];
    const float* conv_w = (const float*)d_in[3];
    const float* conv_b = (const float*)d_in[4];
    const float* A_log  = (const float*)d_in[5];
    const float* B_w    = (const float*)d_in[6];
    const float* C_w    = (const float*)d_in[7];
    const float* dt_w   = (const float*)d_in[8];
    const float* dt_b   = (const float*)d_in[9];
    const float* Dp     = (const float*)d_in[10];
    const float* out_w  = (const float*)d_in[11];
    float* out = (float*)d_out;

    __nv_bfloat16 *p_xn, *p_xs, *p_y, *p_inw, *p_wcat, *p_outw;
    float *p_xz, *p_bcdt;
    cudaGetSymbolAddress((void**)&p_xn, g_xn);
    cudaGetSymbolAddress((void**)&p_xz, g_xz);
    cudaGetSymbolAddress((void**)&p_xs, g_xs);
    cudaGetSymbolAddress((void**)&p_bcdt, g_bcdt);
    cudaGetSymbolAddress((void**)&p_y, g_y);
    cudaGetSymbolAddress((void**)&p_inw, g_inw);
    cudaGetSymbolAddress((void**)&p_wcat, g_wcat);
    cudaGetSymbolAddress((void**)&p_outw, g_outw);

    cudaFuncSetAttribute(gemm_mma<false>, cudaFuncAttributeMaxDynamicSharedMemorySize, GEMM_SMEM);
    cudaFuncSetAttribute(gemm_mma<true>,  cudaFuncAttributeMaxDynamicSharedMemorySize, GEMM_SMEM);

    // weight conversions (bf16)
    cvt_bf16_k<<<256, 256>>>(in_w, p_inw, 2 * DI * DM);
    cvt_bf16_k<<<256, 256>>>(out_w, p_outw, DM * DI);
    build_wcat_k<<<256, 256>>>(B_w, C_w, dt_w);

    // 1. RMSNorm -> bf16
    rmsnorm_k<<<NROWS, 256>>>(x, norm_w);

    // 2. xz = xn @ in_w^T   (4096 x 4096 x 1024)
    gemm_mma<false><<<dim3(4096 / BN2, NROWS / BM), 256, GEMM_SMEM>>>(
        p_xn, p_inw, p_xz, nullptr, NROWS, 2 * DI, DM);

    // 3. causal conv + SiLU -> bf16
    conv_silu_k<<<dim3(DI / 256, TT, BSZ), 256>>>(conv_w, conv_b);

    // 4. [B | C | dt] = xs @ wcat^T   (4096 x 1280 x 2048)
    gemm_mma<false><<<dim3(NCATP / BN2, NROWS / BM), 256, GEMM_SMEM>>>(
        p_xs, p_wcat, p_bcdt, nullptr, NROWS, NCATP, DI);

    // 5. dt softplus
    dt_fin_k<<<(NROWS * NH + 255) / 256, 256>>>(dt_b);

    // 6. selective scan + gating -> bf16
    scan_k<<<dim3(8, NH, BSZ), 256>>>(A_log, Dp);

    // 7. out = y @ out_w^T + residual   (4096 x 1024 x 2048)
    gemm_mma<true><<<dim3(1024 / BN2, NROWS / BM), 256, GEMM_SMEM>>>(
        p_y, p_outw, out, x, NROWS, DM, DI);
}

// round 7
// speedup vs baseline: 1.8828x; 1.8828x over previous
#include <cuda_runtime.h>
#include <cuda_bf16.h>
#include <math.h>
#include <stdint.h>

// ---------------- problem constants ----------------------------------------
#define BSZ 2
#define TT 2048
#define DM 1024
#define DI 2048
#define NH 8
#define DS 64
#define DH 256
#define NROWS (BSZ*TT)          // 4096
#define EPSV 1e-6f
#define NCATP 1280              // B(512) | C(512) | dt(8) | pad

// ---------------- scratch (device globals) ---------------------------------
__device__ __nv_bfloat16 g_xn[(size_t)NROWS * DM];
__device__ float         g_xz[(size_t)NROWS * 2 * DI];
__device__ __nv_bfloat16 g_xs[(size_t)NROWS * DI];
__device__ float         g_bcdt[(size_t)NROWS * NCATP];
__device__ float         g_dt[(size_t)NROWS * NH];
__device__ __nv_bfloat16 g_y [(size_t)NROWS * DI];
__device__ __nv_bfloat16 g_inw [(size_t)(2*DI) * DM];
__device__ __nv_bfloat16 g_wcat[(size_t)NCATP * DI];
__device__ __nv_bfloat16 g_outw[(size_t)DM * DI];

// ---------------- PTX helpers ----------------------------------------------
__device__ __forceinline__ uint32_t smem_u32(const void* p) {
    uint32_t a;
    asm("{ .reg .u64 t; cvta.to.shared.u64 t, %1; cvt.u32.u64 %0, t; }" : "=r"(a) : "l"(p));
    return a;
}

#define CP_ASYNC16(dst, src) \
    asm volatile("cp.async.cg.shared.global [%0], [%1], 16;" :: "r"(dst), "l"(src) : "memory")
#define CP_ASYNC4(dst, src) \
    asm volatile("cp.async.ca.shared.global [%0], [%1], 4;" :: "r"(dst), "l"(src) : "memory")
#define CP_COMMIT() asm volatile("cp.async.commit_group;" ::: "memory")
#define CP_WAIT1()  asm volatile("cp.async.wait_group 1;" ::: "memory")

#define LDM_X4(r0, r1, r2, r3, addr) \
    asm volatile("ldmatrix.sync.aligned.m8n8.x4.shared.b16 {%0,%1,%2,%3}, [%4];" \
                 : "=r"(r0), "=r"(r1), "=r"(r2), "=r"(r3) : "r"(addr))
#define LDM_X2(r0, r1, addr) \
    asm volatile("ldmatrix.sync.aligned.m8n8.x2.shared.b16 {%0,%1}, [%2];" \
                 : "=r"(r0), "=r"(r1) : "r"(addr))

#define MMA16816(d, a0, a1, a2, a3, b0, b1) \
    asm volatile("mma.sync.aligned.m16n8k16.row.col.f32.bf16.bf16.f32 " \
                 "{%0,%1,%2,%3}, {%4,%5,%6,%7}, {%8,%9}, {%0,%1,%2,%3};" \
                 : "+f"((d)[0]), "+f"((d)[1]), "+f"((d)[2]), "+f"((d)[3]) \
                 : "r"(a0), "r"(a1), "r"(a2), "r"(a3), "r"(b0), "r"(b1))

// ---------------- bf16 mma.sync GEMM: C[M,N] = A[M,K] @ W[N,K]^T (+Res) ----
// BM=BN=128, BK=64, 3-stage cp.async ring, 256 threads, 8 warps (2x4),
// warp tile 64x32. One __syncthreads per K-tile; loads overlap compute.
#define BM 128
#define BN 128
#define BK64 64
#define ROWB 144                         // 64*2 + 16 pad bytes
#define SA_BYTES (BM * ROWB)             // 18432
#define STG_BYTES (2 * SA_BYTES)         // 36864 (A + B)
#define NST 3
#define GEMM_SMEM (NST * STG_BYTES)      // 110592

template <bool ADD_RES>
__global__ void __launch_bounds__(256)
gemm_mma(const __nv_bfloat16* __restrict__ A, const __nv_bfloat16* __restrict__ W,
         float* __restrict__ C, const float* __restrict__ Res,
         int M, int N, int K)
{
    extern __shared__ char sm[];
    uint32_t base = smem_u32(sm);

    int tid = threadIdx.x;
    int wid = tid >> 5, lane = tid & 31;
    int wm = wid >> 2, wn = wid & 3;          // 2 x 4 warp grid, tile 64x32
    int m0 = blockIdx.y * BM;
    int n0 = blockIdx.x * BN;

    const __nv_bfloat16* Ag = A + (size_t)m0 * K;
    const __nv_bfloat16* Wg = W + (size_t)n0 * K;

    float acc[4][4][4];
    #pragma unroll
    for (int i = 0; i < 4; i++)
        #pragma unroll
        for (int j = 0; j < 4; j++)
            #pragma unroll
            for (int f = 0; f < 4; f++) acc[i][j][f] = 0.f;

    int nk = K / BK64;

    // stage loader: A and B each 128 rows x 8 16B-chunks = 1024 chunks
    auto load_stage = [&](int s, int k0) {
        uint32_t sA = base + s * STG_BYTES;
        uint32_t sB = sA + SA_BYTES;
        #pragma unroll
        for (int it = 0; it < 4; it++) {
            int i = tid + it * 256;
            int r = i >> 3, c = i & 7;
            CP_ASYNC16(sA + r * ROWB + c * 16, Ag + (size_t)r * K + k0 + c * 8);
        }
        #pragma unroll
        for (int it = 0; it < 4; it++) {
            int i = tid + it * 256;
            int r = i >> 3, c = i & 7;
            CP_ASYNC16(sB + r * ROWB + c * 16, Wg + (size_t)r * K + k0 + c * 8);
        }
    };

    load_stage(0, 0);      CP_COMMIT();
    load_stage(1, BK64);   CP_COMMIT();

    int stg = 0;                      // stage index of tile kt (mod 3)
    for (int kt = 0; kt < nk; kt++) {
        CP_WAIT1();                   // stage kt complete (only stage kt+1 may remain)
        __syncthreads();              // all warps done reading stage kt-1 (being overwritten next)

        // issue loads for tile kt+2 (overlaps with compute below)
        int s2 = stg + 2; if (s2 >= NST) s2 -= NST;
        if (kt + 2 < nk) load_stage(s2, (kt + 2) * BK64);
        CP_COMMIT();                  // always commit (group accounting)

        uint32_t sA = base + stg * STG_BYTES;
        uint32_t sB = sA + SA_BYTES;

        #pragma unroll
        for (int ks = 0; ks < 4; ks++) {
            int colA = ks * 32 + (lane >> 4) * 16;           // bytes
            int colB = ks * 32 + ((lane >> 3) & 1) * 16;     // bytes
            uint32_t a[4][4], b[4][2];
            #pragma unroll
            for (int i = 0; i < 4; i++) {
                int row = wm * 64 + i * 16 + (lane & 15);
                LDM_X4(a[i][0], a[i][1], a[i][2], a[i][3],
                       sA + (uint32_t)(row * ROWB + colA));
            }
            #pragma unroll
            for (int j = 0; j < 4; j++) {
                int row = wn * 32 + j * 8 + (lane & 7);
                LDM_X2(b[j][0], b[j][1],
                       sB + (uint32_t)(row * ROWB + colB));
            }
            #pragma unroll
            for (int i = 0; i < 4; i++)
                #pragma unroll
                for (int j = 0; j < 4; j++)
                    MMA16816(acc[i][j], a[i][0], a[i][1], a[i][2], a[i][3],
                             b[j][0], b[j][1]);
        }
        stg++; if (stg >= NST) stg -= NST;
    }

    // epilogue: direct register -> gmem (float2 per c-frag half)
    int gid = lane >> 2, t4 = lane & 3;
    #pragma unroll
    for (int i = 0; i < 4; i++) {
        int row0 = m0 + wm * 64 + i * 16 + gid;
        #pragma unroll
        for (int j = 0; j < 4; j++) {
            int col = n0 + wn * 32 + j * 8 + t4 * 2;
            size_t i0 = (size_t)row0 * N + col;
            size_t i1 = (size_t)(row0 + 8) * N + col;
            float2 v0 = make_float2(acc[i][j][0], acc[i][j][1]);
            float2 v1 = make_float2(acc[i][j][2], acc[i][j][3]);
            if (ADD_RES) {
                float2 r0 = *(const float2*)(Res + i0);
                float2 r1 = *(const float2*)(Res + i1);
                v0.x += r0.x; v0.y += r0.y;
                v1.x += r1.x; v1.y += r1.y;
            }
            *(float2*)(C + i0) = v0;
            *(float2*)(C + i1) = v1;
        }
    }
}

// ---------------- weight conversion ----------------------------------------
__global__ void cvt_bf16_k(const float* __restrict__ in, __nv_bfloat16* __restrict__ out, int n)
{
    for (int i = blockIdx.x * 256 + threadIdx.x; i < n; i += gridDim.x * 256)
        out[i] = __float2bfloat16(in[i]);
}

__global__ void build_wcat_k(const float* __restrict__ Bw, const float* __restrict__ Cw,
                             const float* __restrict__ dtw)
{
    int n = NCATP * DI;
    for (int i = blockIdx.x * 256 + threadIdx.x; i < n; i += gridDim.x * 256) {
        int r = i >> 11, k = i & (DI - 1);
        float v;
        if (r < 512)       v = Bw[(size_t)r * DI + k];
        else if (r < 1024) v = Cw[(size_t)(r - 512) * DI + k];
        else if (r < 1032) v = dtw[(size_t)(r - 1024) * DI + k];
        else               v = 0.f;
        g_wcat[i] = __float2bfloat16(v);
    }
}

// ---------------- RMSNorm (writes bf16) -------------------------------------
__global__ void rmsnorm_k(const float* __restrict__ x, const float* __restrict__ w)
{
    int row = blockIdx.x;
    const float* xr = x + (size_t)row * DM;
    float s = 0.f;
    for (int i = threadIdx.x; i < DM; i += 256) { float v = xr[i]; s += v * v; }
    __shared__ float red[8];
    #pragma unroll
    for (int o = 16; o; o >>= 1) s += __shfl_xor_sync(0xffffffffu, s, o);
    if ((threadIdx.x & 31) == 0) red[threadIdx.x >> 5] = s;
    __syncthreads();
    if (threadIdx.x < 8) {
        float v = red[threadIdx.x];
        #pragma unroll
        for (int o = 4; o; o >>= 1) v += __shfl_xor_sync(0xffu, v, o);
        if (threadIdx.x == 0) red[0] = rsqrtf(v / (float)DM + EPSV);
    }
    __syncthreads();
    float sc = red[0];
    for (int i = threadIdx.x; i < DM; i += 256)
        g_xn[(size_t)row * DM + i] = __float2bfloat16(xr[i] * sc * w[i]);
}

// ---------------- causal depthwise conv (K=4) + bias + SiLU -> bf16 ---------
__global__ void conv_silu_k(const float* __restrict__ cw, const float* __restrict__ cb)
{
    int c = blockIdx.x * 256 + threadIdx.x;
    int t = blockIdx.y;
    int b = blockIdx.z;
    float4 w = ((const float4*)cw)[c];
    float acc = cb[c];
    size_t colbase = (size_t)b * TT * (2 * DI) + c;
    const size_t stride = 2 * DI;
    if (t >= 3) acc += w.x * g_xz[colbase + (size_t)(t - 3) * stride];
    if (t >= 2) acc += w.y * g_xz[colbase + (size_t)(t - 2) * stride];
    if (t >= 1) acc += w.z * g_xz[colbase + (size_t)(t - 1) * stride];
    acc += w.w * g_xz[colbase + (size_t)t * stride];
    float sig = 1.f / (1.f + expf(-acc));
    g_xs[((size_t)b * TT + t) * DI + c] = __float2bfloat16(acc * sig);
}

// ---------------- dt finalize: softplus(raw + bias) -------------------------
__global__ void dt_fin_k(const float* __restrict__ dtb)
{
    int i = blockIdx.x * 256 + threadIdx.x;
    if (i < NROWS * NH) {
        int row = i >> 3, h = i & 7;
        float v = g_bcdt[(size_t)row * NCATP + 1024 + h] + dtb[h];
        g_dt[i] = (v > 20.f) ? v : log1pf(expf(v));
    }
}

// ---------------- selective scan v2: smem-staged chunks ---------------------
// grid: (d_tile=8, h=8, b=2), 256 threads. CHUNK=32 timesteps double-buffered
// via cp.async; inner loop reads smem only.
#define SCH 32
#define NCHUNK (TT / SCH)    // 64

__global__ void __launch_bounds__(256)
scan_k(const float* __restrict__ A_log, const float* __restrict__ Dp)
{
    __shared__ float Bs[2][SCH][64];
    __shared__ float Cs[2][SCH][64];
    __shared__ float Zs[2][SCH][32];
    __shared__ __nv_bfloat16 Xs[2][SCH][32];
    __shared__ float Dts[2][SCH];

    int tid = threadIdx.x;
    int dtile = blockIdx.x;
    int h = blockIdx.y;
    int b = blockIdx.z;
    int warp = tid >> 5, lane = tid & 31;
    int dl = lane & 3;
    int ng = lane >> 2;                 // 0..7
    int li = warp * 4 + dl;             // 0..31 local d index
    int d = dtile * 32 + li;
    int nbase = ng * 8;

    size_t rb = (size_t)b * TT;
    int xoff = h * DH + d;

    // chunk loader (all global -> smem via cp.async)
    auto load_chunk = [&](int c) {
        int bb = c & 1;
        size_t t0 = rb + (size_t)c * SCH;
        const float* bsrc = g_bcdt + t0 * NCATP + h * 64;
        const float* csrc = bsrc + 512;
        const float* zsrc = g_xz + t0 * (2 * DI) + DI + h * DH + dtile * 32;
        const __nv_bfloat16* xsrc = g_xs + t0 * DI + h * DH + dtile * 32;
        for (int i = tid; i < 1408; i += 256) {
            if (i < 512) {
                int tl = i >> 4, p = i & 15;
                CP_ASYNC16(smem_u32(&Bs[bb][tl][p * 4]), bsrc + (size_t)tl * NCATP + p * 4);
            } else if (i < 1024) {
                int tl = (i - 512) >> 4, p = (i - 512) & 15;
                CP_ASYNC16(smem_u32(&Cs[bb][tl][p * 4]), csrc + (size_t)tl * NCATP + p * 4);
            } else if (i < 1280) {
                int tl = (i - 1024) >> 3, p = (i - 1024) & 7;
                CP_ASYNC16(smem_u32(&Zs[bb][tl][p * 4]), zsrc + (size_t)tl * (2 * DI) + p * 4);
            } else {
                int tl = (i - 1280) >> 2, p = (i - 1280) & 3;
                CP_ASYNC16(smem_u32(&Xs[bb][tl][p * 8]), xsrc + (size_t)tl * DI + p * 8);
            }
        }
        if (tid < SCH)
            CP_ASYNC4(smem_u32(&Dts[bb][tid]), g_dt + (t0 + tid) * NH + h);
    };

    float A = -expf(A_log[h]);
    float Dh = Dp[h];
    float hs[8];
    #pragma unroll
    for (int j = 0; j < 8; j++) hs[j] = 0.f;

    load_chunk(0); CP_COMMIT();

    for (int c = 0; c < NCHUNK; c++) {
        if (c + 1 < NCHUNK) load_chunk(c + 1);
        CP_COMMIT();
        CP_WAIT1();
        __syncthreads();

        int bb = c & 1;
        size_t orow = rb + (size_t)c * SCH;
        #pragma unroll 4
        for (int tl = 0; tl < SCH; tl++) {
            float dtv = Dts[bb][tl];
            float4 b0 = *(const float4*)&Bs[bb][tl][nbase];
            float4 b1 = *(const float4*)&Bs[bb][tl][nbase + 4];
            float4 c0 = *(const float4*)&Cs[bb][tl][nbase];
            float4 c1 = *(const float4*)&Cs[bb][tl][nbase + 4];
            float xd = __bfloat162float(Xs[bb][tl][li]);

            float dA = __expf(dtv * A);
            float dtx = dtv * xd;
            float acc;
            hs[0] = dA * hs[0] + b0.x * dtx; acc  = c0.x * hs[0];
            hs[1] = dA * hs[1] + b0.y * dtx; acc += c0.y * hs[1];
            hs[2] = dA * hs[2] + b0.z * dtx; acc += c0.z * hs[2];
            hs[3] = dA * hs[3] + b0.w * dtx; acc += c0.w * hs[3];
            hs[4] = dA * hs[4] + b1.x * dtx; acc += c1.x * hs[4];
            hs[5] = dA * hs[5] + b1.y * dtx; acc += c1.y * hs[5];
            hs[6] = dA * hs[6] + b1.z * dtx; acc += c1.z * hs[6];
            hs[7] = dA * hs[7] + b1.w * dtx; acc += c1.w * hs[7];

            acc += __shfl_xor_sync(0xffffffffu, acc, 16);
            acc += __shfl_xor_sync(0xffffffffu, acc, 8);
            acc += __shfl_xor_sync(0xffffffffu, acc, 4);

            if (ng == 0) {
                float zv = Zs[bb][tl][li];
                float sig = 1.f / (1.f + __expf(-zv));
                g_y[(orow + tl) * DI + xoff] = __float2bfloat16((acc + Dh * xd) * (zv * sig));
            }
        }
        __syncthreads();
    }
}

// ---------------- launch ----------------------------------------------------
extern "C" void kernel_launch(void* const* d_in, const int* in_sizes, int n_in,
                              void* d_out, int out_size)
{
    const float* x      = (const float*)d_in[0];
    const float* norm_w = (const float*)d_in[1];
    const float* in_w   = (const float*)d_in[2];
    const float* conv_w = (const float*)d_in[3];
    const float* conv_b = (const float*)d_in[4];
    const float* A_log  = (const float*)d_in[5];
    const float* B_w    = (const float*)d_in[6];
    const float* C_w    = (const float*)d_in[7];
    const float* dt_w   = (const float*)d_in[8];
    const float* dt_b   = (const float*)d_in[9];
    const float* Dp     = (const float*)d_in[10];
    const float* out_w  = (const float*)d_in[11];
    float* out = (float*)d_out;

    __nv_bfloat16 *p_xn, *p_xs, *p_y, *p_inw, *p_wcat, *p_outw;
    float *p_xz, *p_bcdt;
    cudaGetSymbolAddress((void**)&p_xn, g_xn);
    cudaGetSymbolAddress((void**)&p_xz, g_xz);
    cudaGetSymbolAddress((void**)&p_xs, g_xs);
    cudaGetSymbolAddress((void**)&p_bcdt, g_bcdt);
    cudaGetSymbolAddress((void**)&p_y, g_y);
    cudaGetSymbolAddress((void**)&p_inw, g_inw);
    cudaGetSymbolAddress((void**)&p_wcat, g_wcat);
    cudaGetSymbolAddress((void**)&p_outw, g_outw);

    cudaFuncSetAttribute(gemm_mma<false>, cudaFuncAttributeMaxDynamicSharedMemorySize, GEMM_SMEM);
    cudaFuncSetAttribute(gemm_mma<true>,  cudaFuncAttributeMaxDynamicSharedMemorySize, GEMM_SMEM);

    // weight conversions (bf16)
    cvt_bf16_k<<<256, 256>>>(in_w, p_inw, 2 * DI * DM);
    cvt_bf16_k<<<256, 256>>>(out_w, p_outw, DM * DI);
    build_wcat_k<<<256, 256>>>(B_w, C_w, dt_w);

    // 1. RMSNorm -> bf16
    rmsnorm_k<<<NROWS, 256>>>(x, norm_w);

    // 2. xz = xn @ in_w^T   (4096 x 4096 x 1024)
    gemm_mma<false><<<dim3(4096 / BN, NROWS / BM), 256, GEMM_SMEM>>>(
        p_xn, p_inw, p_xz, nullptr, NROWS, 2 * DI, DM);

    // 3. causal conv + SiLU -> bf16
    conv_silu_k<<<dim3(DI / 256, TT, BSZ), 256>>>(conv_w, conv_b);

    // 4. [B | C | dt] = xs @ wcat^T   (4096 x 1280 x 2048)
    gemm_mma<false><<<dim3(NCATP / BN, NROWS / BM), 256, GEMM_SMEM>>>(
        p_xs, p_wcat, p_bcdt, nullptr, NROWS, NCATP, DI);

    // 5. dt softplus
    dt_fin_k<<<(NROWS * NH + 255) / 256, 256>>>(dt_b);

    // 6. selective scan + gating -> bf16 (smem-staged)
    scan_k<<<dim3(8, NH, BSZ), 256>>>(A_log, Dp);

    // 7. out = y @ out_w^T + residual   (4096 x 1024 x 2048)
    gemm_mma<true><<<dim3(1024 / BN, NROWS / BM), 256, GEMM_SMEM>>>(
        p_y, p_outw, out, x, NROWS, DM, DI);
}